// round 1
// baseline (speedup 1.0000x reference)
#include <cuda_runtime.h>
#include <math.h>

// Problem constants
#define BB 2
#define LL 4096
#define DD 512
#define HH 8
#define EE 64
#define CC 64              // chunk length
#define NC (LL/CC)         // 64 chunks
#define MM (BB*LL)         // 8192 rows

// ---------------- scratch (device globals; no allocation) ----------------
__device__ float g_q[MM*DD];                 // q features (elu+1)/8, later *exp(cum)
__device__ float g_k[MM*DD];                 // k features (elu+1),   later *exp(-cum)
__device__ float g_v[MM*DD];
__device__ float g_loglam[MM*HH];
__device__ float g_cum[MM*HH];               // clipped cumulative log-lambda
__device__ float g_state[(size_t)BB*HH*NC*EE*EE];   // per-chunk KV states -> exclusive prefix
__device__ float g_zstate[BB*HH*NC*EE];              // per-chunk k sums   -> exclusive prefix
__device__ float g_attn[MM*DD];              // attention output (B,L,D)
__device__ float g_proj[MM*DD];              // after out projection, pre-norm

// ---------------- GEMM: C = A @ W^T + bias, 64x64 tiles, fp32 ----------------
// MODE 0: A = x, N=1536, epilogue splits into q/k/v with feature maps
// MODE 1: A = g_attn, N=512, epilogue writes g_proj with bias
template<int MODE>
__global__ __launch_bounds__(256)
void gemm64(const float* __restrict__ Ain, const float* __restrict__ W,
            const float* __restrict__ bias)
{
    const int K = DD;
    const float* A = (MODE == 0) ? Ain : g_attn;
    __shared__ float As[16][68];
    __shared__ float Ws[16][68];
    const int bm = blockIdx.y * 64;
    const int bn = blockIdx.x * 64;
    const int tid = threadIdx.x;
    const int lr = tid >> 2;            // 0..63 row within tile
    const int lk = (tid & 3) << 2;      // 0,4,8,12 k offset
    const int ty = tid >> 4;            // 0..15
    const int tx = tid & 15;            // 0..15

    float acc[4][4];
#pragma unroll
    for (int i = 0; i < 4; i++)
#pragma unroll
        for (int j = 0; j < 4; j++) acc[i][j] = 0.f;

    for (int k0 = 0; k0 < K; k0 += 16) {
        float4 a = *(const float4*)(A + (size_t)(bm + lr) * K + k0 + lk);
        float4 w = *(const float4*)(W + (size_t)(bn + lr) * K + k0 + lk);
        As[lk + 0][lr] = a.x; As[lk + 1][lr] = a.y; As[lk + 2][lr] = a.z; As[lk + 3][lr] = a.w;
        Ws[lk + 0][lr] = w.x; Ws[lk + 1][lr] = w.y; Ws[lk + 2][lr] = w.z; Ws[lk + 3][lr] = w.w;
        __syncthreads();
#pragma unroll
        for (int kk = 0; kk < 16; kk++) {
            float af[4], wf[4];
            *(float4*)af = *(const float4*)&As[kk][ty << 2];
            *(float4*)wf = *(const float4*)&Ws[kk][tx << 2];
#pragma unroll
            for (int i = 0; i < 4; i++)
#pragma unroll
                for (int j = 0; j < 4; j++)
                    acc[i][j] = fmaf(af[i], wf[j], acc[i][j]);
        }
        __syncthreads();
    }

    const int n0 = bn + (tx << 2);
    if (MODE == 0) {
        const int sec = n0 >> 9;        // 0:q 1:k 2:v (64-wide tile never straddles)
        const int col = n0 & 511;
        float* dst = (sec == 0) ? g_q : (sec == 1) ? g_k : g_v;
#pragma unroll
        for (int i = 0; i < 4; i++) {
            const int m = bm + (ty << 2) + i;
            float r[4];
#pragma unroll
            for (int j = 0; j < 4; j++) {
                float v = acc[i][j] + bias[n0 + j];
                if (sec == 0) v = (v > 0.f) ? (v + 1.f) * 0.125f : expf(v) * 0.125f;
                else if (sec == 1) v = (v > 0.f) ? (v + 1.f) : expf(v);
                r[j] = v;
            }
            float4 o; o.x = r[0]; o.y = r[1]; o.z = r[2]; o.w = r[3];
            *(float4*)(dst + (size_t)m * DD + col) = o;
        }
    } else {
#pragma unroll
        for (int i = 0; i < 4; i++) {
            const int m = bm + (ty << 2) + i;
            float4 o;
            o.x = acc[i][0] + bias[n0 + 0];
            o.y = acc[i][1] + bias[n0 + 1];
            o.z = acc[i][2] + bias[n0 + 2];
            o.w = acc[i][3] + bias[n0 + 3];
            *(float4*)(g_proj + (size_t)m * DD + n0) = o;
        }
    }
}

// ---------------- decay logits -> log(lambda) ----------------
__global__ __launch_bounds__(256)
void decay_kernel(const float* __restrict__ x, const float* __restrict__ dw,
                  const float* __restrict__ db)
{
    const int m = blockIdx.x;
    const int h = threadIdx.x >> 5;
    const int lane = threadIdx.x & 31;
    const float* xr = x + (size_t)m * DD;
    const float* wr = dw + h * DD;
    float s = 0.f;
    for (int k = lane * 4; k < DD; k += 128) {
        float4 xv = *(const float4*)(xr + k);
        float4 wv = *(const float4*)(wr + k);
        s += xv.x * wv.x + xv.y * wv.y + xv.z * wv.z + xv.w * wv.w;
    }
#pragma unroll
    for (int off = 16; off; off >>= 1) s += __shfl_xor_sync(0xffffffffu, s, off);
    if (lane == 0) {
        float logit = s + db[h];
        float lam = 0.9f + 0.1f / (1.f + expf(-logit));
        g_loglam[m * HH + h] = logf(lam);
    }
}

// ---------------- cumsum of log-lambda along L (per b,h), clipped ----------------
__global__ __launch_bounds__(256)
void cumsum_kernel()
{
    const int b = blockIdx.x >> 3;
    const int h = blockIdx.x & 7;
    const int tid = threadIdx.x;
    float vals[16];
    float s = 0.f;
    const int base = (b * LL + tid * 16) * HH + h;
#pragma unroll
    for (int i = 0; i < 16; i++) { s += g_loglam[base + i * HH]; vals[i] = s; }
    __shared__ float ts[256];
    ts[tid] = s;
    __syncthreads();
    for (int off = 1; off < 256; off <<= 1) {
        float v = (tid >= off) ? ts[tid - off] : 0.f;
        __syncthreads();
        ts[tid] += v;
        __syncthreads();
    }
    const float prev = (tid > 0) ? ts[tid - 1] : 0.f;
#pragma unroll
    for (int i = 0; i < 16; i++) {
        float c = prev + vals[i];
        c = fminf(50.f, fmaxf(-50.f, c));
        g_cum[base + i * HH] = c;
    }
}

// ---------------- apply decay to q and k in place ----------------
__global__ __launch_bounds__(256)
void applydecay_kernel()
{
    const int idx4 = blockIdx.x * 256 + threadIdx.x;  // float4 index into (M,D)
    const int m = idx4 >> 7;
    const int d4 = idx4 & 127;
    const int h = d4 >> 4;                            // E/4 = 16 float4 per head
    const float c = g_cum[m * HH + h];
    const float eq = __expf(c);
    const float ek = __expf(-c);
    float4* qp = (float4*)g_q + idx4;
    float4* kp = (float4*)g_k + idx4;
    float4 q = *qp; q.x *= eq; q.y *= eq; q.z *= eq; q.w *= eq; *qp = q;
    float4 k = *kp; k.x *= ek; k.y *= ek; k.z *= ek; k.w *= ek; *kp = k;
}

// ---------------- per-chunk KV state and k-sum ----------------
__global__ __launch_bounds__(256)
void chunkstate_kernel()
{
    const int c = blockIdx.x & (NC - 1);
    const int h = (blockIdx.x >> 6) & 7;
    const int b = blockIdx.x >> 9;
    __shared__ float ks[8][64];
    __shared__ float vs[8][64];
    const int tid = threadIdx.x;
    const int e0 = (tid >> 4) << 2;
    const int f0 = (tid & 15) << 2;
    float acc[4][4];
#pragma unroll
    for (int i = 0; i < 4; i++)
#pragma unroll
        for (int j = 0; j < 4; j++) acc[i][j] = 0.f;
    float z = 0.f;
    const int rowbase = b * LL + c * CC;

    for (int t0 = 0; t0 < CC; t0 += 8) {
#pragma unroll
        for (int it = 0; it < 2; it++) {
            int idx = tid + it * 256;
            int tt = idx >> 6;
            int ee = idx & 63;
            size_t g = (size_t)(rowbase + t0 + tt) * DD + h * EE + ee;
            ks[tt][ee] = g_k[g];
            vs[tt][ee] = g_v[g];
        }
        __syncthreads();
#pragma unroll
        for (int t = 0; t < 8; t++) {
            float kf[4], vf[4];
#pragma unroll
            for (int i = 0; i < 4; i++) kf[i] = ks[t][e0 + i];
#pragma unroll
            for (int j = 0; j < 4; j++) vf[j] = vs[t][f0 + j];
#pragma unroll
            for (int i = 0; i < 4; i++)
#pragma unroll
                for (int j = 0; j < 4; j++)
                    acc[i][j] = fmaf(kf[i], vf[j], acc[i][j]);
            if (tid < 64) z += ks[t][tid];
        }
        __syncthreads();
    }
    const int bh = b * HH + h;
    const size_t sbase = ((size_t)bh * NC + c) * (EE * EE);
#pragma unroll
    for (int i = 0; i < 4; i++) {
        float4 o; o.x = acc[i][0]; o.y = acc[i][1]; o.z = acc[i][2]; o.w = acc[i][3];
        *(float4*)(g_state + sbase + (e0 + i) * EE + f0) = o;
    }
    if (tid < 64) g_zstate[(bh * NC + c) * EE + tid] = z;
}

// ---------------- exclusive scan over chunks (states + zsums) ----------------
__global__ __launch_bounds__(256)
void statescan_kernel()
{
    const int bh = blockIdx.x >> 4;
    const int split = blockIdx.x & 15;
    const int elem = split * 256 + threadIdx.x;   // 0..4095
    size_t base = (size_t)bh * NC * EE * EE + elem;
    float run = 0.f;
#pragma unroll 4
    for (int c = 0; c < NC; c++) {
        float v = g_state[base + (size_t)c * EE * EE];
        g_state[base + (size_t)c * EE * EE] = run;
        run += v;
    }
    if (split == 0 && threadIdx.x < 64) {
        size_t zb = (size_t)bh * NC * EE + threadIdx.x;
        float r = 0.f;
        for (int c = 0; c < NC; c++) {
            float v = g_zstate[zb + (size_t)c * EE];
            g_zstate[zb + (size_t)c * EE] = r;
            r += v;
        }
    }
}

// ---------------- intra-chunk attention + inter via prefix state ----------------
__global__ __launch_bounds__(256)
void intra_kernel()
{
    extern __shared__ float sm[];
    float* qs = sm;                      // [64][68]
    float* ks = sm + 64 * 68;            // [64][68], reused for S after phase 1
    float* vs = sm + 2 * 64 * 68;        // [64][68]
    float* As = sm + 3 * 64 * 68;        // [64][68]
    float* den_s = sm + 4 * 64 * 68;     // [64] reciprocal denominators
    float* zsh = den_s + 64;             // [64]

    const int c = blockIdx.x & (NC - 1);
    const int h = (blockIdx.x >> 6) & 7;
    const int b = blockIdx.x >> 9;
    const int bh = b * HH + h;
    const int tid = threadIdx.x;
    const int rowbase = b * LL + c * CC;

    // phase 0: load q,k,v chunk tiles + z prefix
#pragma unroll
    for (int it = 0; it < 4; it++) {
        int idx = tid + it * 256;        // float4 index 0..1023
        int t = idx >> 4;
        int e4 = (idx & 15) << 2;
        size_t g = (size_t)(rowbase + t) * DD + h * EE + e4;
        *(float4*)&qs[t * 68 + e4] = *(const float4*)(g_q + g);
        *(float4*)&ks[t * 68 + e4] = *(const float4*)(g_k + g);
        *(float4*)&vs[t * 68 + e4] = *(const float4*)(g_v + g);
    }
    if (tid < 64) zsh[tid] = g_zstate[(bh * NC + c) * EE + tid];
    __syncthreads();

    const int t0 = (tid >> 4) << 2;
    const int s0 = (tid & 15) << 2;

    // phase 1: A = q k^T with causal mask (s <= t)
    {
        float a[4][4];
#pragma unroll
        for (int i = 0; i < 4; i++)
#pragma unroll
            for (int j = 0; j < 4; j++) a[i][j] = 0.f;
        for (int e = 0; e < EE; e += 4) {
            float4 qv[4], kv[4];
#pragma unroll
            for (int i = 0; i < 4; i++) qv[i] = *(const float4*)&qs[(t0 + i) * 68 + e];
#pragma unroll
            for (int j = 0; j < 4; j++) kv[j] = *(const float4*)&ks[(s0 + j) * 68 + e];
#pragma unroll
            for (int i = 0; i < 4; i++)
#pragma unroll
                for (int j = 0; j < 4; j++)
                    a[i][j] += qv[i].x * kv[j].x + qv[i].y * kv[j].y
                             + qv[i].z * kv[j].z + qv[i].w * kv[j].w;
        }
#pragma unroll
        for (int i = 0; i < 4; i++) {
            float r[4];
#pragma unroll
            for (int j = 0; j < 4; j++)
                r[j] = (s0 + j <= t0 + i) ? a[i][j] : 0.f;
            float4 o; o.x = r[0]; o.y = r[1]; o.z = r[2]; o.w = r[3];
            *(float4*)&As[(t0 + i) * 68 + s0] = o;
        }
    }
    __syncthreads();

    // phase 2: overwrite ks region with S prefix; tid<64 compute denominators
    {
        const size_t sb = ((size_t)bh * NC + c) * (EE * EE);
#pragma unroll
        for (int it = 0; it < 4; it++) {
            int idx = tid + it * 256;
            int e = idx >> 4;
            int f4 = (idx & 15) << 2;
            *(float4*)&ks[e * 68 + f4] = *(const float4*)(g_state + sb + e * EE + f4);
        }
        if (tid < 64) {
            const int t = tid;
            float s = 0.f;
            for (int s2 = 0; s2 <= t; s2++) s += As[t * 68 + s2];
            for (int e = 0; e < EE; e++) s += qs[t * 68 + e] * zsh[e];
            den_s[t] = 1.f / (s + 1e-6f);
        }
    }
    __syncthreads();

    // phase 3: num = A @ v + q @ S; write out = num * rden
    {
        float acc[4][4];
#pragma unroll
        for (int i = 0; i < 4; i++)
#pragma unroll
            for (int j = 0; j < 4; j++) acc[i][j] = 0.f;

        // intra: contraction over s
        for (int s = 0; s < CC; s += 4) {
            float av[4][4], vv[4][4];
#pragma unroll
            for (int i = 0; i < 4; i++)
#pragma unroll
                for (int m2 = 0; m2 < 4; m2++)
                    av[i][m2] = As[(t0 + i) * 68 + s + m2];
#pragma unroll
            for (int m2 = 0; m2 < 4; m2++)
#pragma unroll
                for (int j = 0; j < 4; j++)
                    vv[m2][j] = vs[(s + m2) * 68 + s0 + j];
#pragma unroll
            for (int i = 0; i < 4; i++)
#pragma unroll
                for (int m2 = 0; m2 < 4; m2++)
#pragma unroll
                    for (int j = 0; j < 4; j++)
                        acc[i][j] = fmaf(av[i][m2], vv[m2][j], acc[i][j]);
        }
        // inter: contraction over e with S (in ks region)
        for (int e = 0; e < EE; e += 4) {
            float qv[4][4], Sv[4][4];
#pragma unroll
            for (int i = 0; i < 4; i++)
#pragma unroll
                for (int m2 = 0; m2 < 4; m2++)
                    qv[i][m2] = qs[(t0 + i) * 68 + e + m2];
#pragma unroll
            for (int m2 = 0; m2 < 4; m2++)
#pragma unroll
                for (int j = 0; j < 4; j++)
                    Sv[m2][j] = ks[(e + m2) * 68 + s0 + j];
#pragma unroll
            for (int i = 0; i < 4; i++)
#pragma unroll
                for (int m2 = 0; m2 < 4; m2++)
#pragma unroll
                    for (int j = 0; j < 4; j++)
                        acc[i][j] = fmaf(qv[i][m2], Sv[m2][j], acc[i][j]);
        }
#pragma unroll
        for (int i = 0; i < 4; i++) {
            const float rd = den_s[t0 + i];
            const int row = rowbase + t0 + i;
            float4 o;
            o.x = acc[i][0] * rd; o.y = acc[i][1] * rd;
            o.z = acc[i][2] * rd; o.w = acc[i][3] * rd;
            *(float4*)(g_attn + (size_t)row * DD + h * EE + s0) = o;
        }
    }
}

// ---------------- RMSNorm ----------------
__global__ __launch_bounds__(128)
void rmsnorm_kernel(const float* __restrict__ scale, float* __restrict__ out)
{
    const int m = blockIdx.x;
    const int tid = threadIdx.x;
    float4 v = *(const float4*)(g_proj + (size_t)m * DD + tid * 4);
    float ss = v.x * v.x + v.y * v.y + v.z * v.z + v.w * v.w;
#pragma unroll
    for (int off = 16; off; off >>= 1) ss += __shfl_xor_sync(0xffffffffu, ss, off);
    __shared__ float ws[4];
    if ((tid & 31) == 0) ws[tid >> 5] = ss;
    __syncthreads();
    float tot = ws[0] + ws[1] + ws[2] + ws[3];
    float rn = rsqrtf(tot * (1.f / DD) + 1e-8f);
    float4 sc = *(const float4*)(scale + tid * 4);
    float4 o;
    o.x = v.x * rn * sc.x; o.y = v.y * rn * sc.y;
    o.z = v.z * rn * sc.z; o.w = v.w * rn * sc.w;
    *(float4*)(out + (size_t)m * DD + tid * 4) = o;
}

// ---------------- launch ----------------
extern "C" void kernel_launch(void* const* d_in, const int* in_sizes, int n_in,
                              void* d_out, int out_size)
{
    const float* x          = (const float*)d_in[0];
    const float* qkv_w      = (const float*)d_in[1];
    const float* qkv_b      = (const float*)d_in[2];
    const float* out_w      = (const float*)d_in[3];
    const float* out_b      = (const float*)d_in[4];
    const float* decay_w    = (const float*)d_in[5];
    const float* decay_b    = (const float*)d_in[6];
    const float* norm_scale = (const float*)d_in[7];
    float* out = (float*)d_out;

    gemm64<0><<<dim3(24, 128), 256>>>(x, qkv_w, qkv_b);
    decay_kernel<<<MM, 256>>>(x, decay_w, decay_b);
    cumsum_kernel<<<BB * HH, 256>>>();
    applydecay_kernel<<<(MM * DD) / 1024, 256>>>();
    chunkstate_kernel<<<BB * HH * NC, 256>>>();
    statescan_kernel<<<BB * HH * 16, 256>>>();

    const int ism = (4 * 64 * 68 + 128) * (int)sizeof(float);   // ~70 KB
    cudaFuncSetAttribute(intra_kernel, cudaFuncAttributeMaxDynamicSharedMemorySize, ism);
    intra_kernel<<<BB * HH * NC, 256, ism>>>();

    gemm64<1><<<dim3(8, 128), 256>>>(nullptr, out_w, out_b);
    rmsnorm_kernel<<<MM, 128>>>(norm_scale, out);
}

// round 3
// speedup vs baseline: 2.1909x; 2.1909x over previous
#include <cuda_runtime.h>
#include <math.h>
#include <stdint.h>

// Problem constants
#define BB 2
#define LL 4096
#define DD 512
#define HH 8
#define EE 64
#define CC 64              // chunk length
#define NC (LL/CC)         // 64 chunks
#define MM (BB*LL)         // 8192 rows

// ---------------- scratch (device globals; no allocation) ----------------
__device__ float g_q[MM*DD];
__device__ float g_k[MM*DD];
__device__ float g_v[MM*DD];
__device__ float g_loglam[MM*HH];
__device__ float g_cum[MM*HH];
__device__ float g_state[(size_t)BB*HH*NC*EE*EE];
__device__ float g_zstate[BB*HH*NC*EE];
__device__ float g_attn[MM*DD];
__device__ float g_proj[MM*DD];

// ---------------- tf32 helpers ----------------
__device__ __forceinline__ uint32_t f2tf32(float f) {
    uint32_t u;
    asm("cvt.rna.tf32.f32 %0, %1;" : "=r"(u) : "f"(f));
    return u;
}
__device__ __forceinline__ void mma_tf32(float c[4], const uint32_t a[4],
                                         uint32_t b0, uint32_t b1) {
    asm volatile(
        "mma.sync.aligned.m16n8k8.row.col.f32.tf32.tf32.f32 "
        "{%0,%1,%2,%3}, {%4,%5,%6,%7}, {%8,%9}, {%0,%1,%2,%3};"
        : "+f"(c[0]), "+f"(c[1]), "+f"(c[2]), "+f"(c[3])
        : "r"(a[0]), "r"(a[1]), "r"(a[2]), "r"(a[3]), "r"(b0), "r"(b1));
}
__device__ __forceinline__ void cp_async16(uint32_t s, const void* g) {
    asm volatile("cp.async.ca.shared.global [%0], [%1], 16;" :: "r"(s), "l"(g));
}
__device__ __forceinline__ void cp_commit() {
    asm volatile("cp.async.commit_group;");
}
template<int N>
__device__ __forceinline__ void cp_wait() {
    asm volatile("cp.async.wait_group %0;" :: "n"(N));
}

// ---------------- tensor-core GEMM: C = A @ W^T + bias ----------------
// 128x128 block tile, K=512, tf32 mma, cp.async double buffer.
// MODE 0: A = x (N=1536), epilogue: qkv split + elu feature map + fused decay
// MODE 1: A = g_attn (N=512), epilogue: bias -> g_proj
#define SPITCH 36
#define ASZ (128 * SPITCH)

template<int MODE>
__global__ __launch_bounds__(256, 2)
void gemm_tc(const float* __restrict__ Ain, const float* __restrict__ W,
             const float* __restrict__ bias)
{
    extern __shared__ float sm[];
    const float* A = (MODE == 0) ? Ain : g_attn;

    const int tid  = threadIdx.x;
    const int w    = tid >> 5;
    const int lane = tid & 31;
    const int g    = lane >> 2;
    const int tig  = lane & 3;
    const int warpM = (w & 3) * 32;
    const int warpN = (w >> 2) * 64;
    const int bm = blockIdx.y * 128;
    const int bn = blockIdx.x * 128;

    float acc[2][8][4];
#pragma unroll
    for (int mt = 0; mt < 2; mt++)
#pragma unroll
        for (int nt = 0; nt < 8; nt++)
#pragma unroll
            for (int i = 0; i < 4; i++) acc[mt][nt][i] = 0.f;

    // per-thread load slots: 4 float4 for A, 4 for W per chunk
    const int lrow0 = tid >> 3;          // 0..31 (x4 via i)  => rows: lrow0 + 32*i
    const int lcol  = (tid & 7) * 4;     // k offset 0..28

    uint32_t sbase;
    {
        void* p = sm;
        sbase = (uint32_t)__cvta_generic_to_shared(p);
    }
    auto stage_issue = [&](int kc, int st) {
        uint32_t as = sbase + (uint32_t)(st * 2 * ASZ) * 4u;
        uint32_t ws = as + (uint32_t)ASZ * 4u;
#pragma unroll
        for (int i = 0; i < 4; i++) {
            int row = lrow0 + i * 32;
            cp_async16(as + (uint32_t)(row * SPITCH + lcol) * 4u,
                       A + (size_t)(bm + row) * DD + kc * 32 + lcol);
            cp_async16(ws + (uint32_t)(row * SPITCH + lcol) * 4u,
                       W + (size_t)(bn + row) * DD + kc * 32 + lcol);
        }
        cp_commit();
    };

    stage_issue(0, 0);

    const int NKC = DD / 32;   // 16
    for (int kc = 0; kc < NKC; kc++) {
        if (kc + 1 < NKC) {
            stage_issue(kc + 1, (kc + 1) & 1);
            cp_wait<1>();
        } else {
            cp_wait<0>();
        }
        __syncthreads();

        const float* As = sm + (kc & 1) * 2 * ASZ;
        const float* Ws = As + ASZ;

#pragma unroll
        for (int kk = 0; kk < 4; kk++) {
            const int k0 = kk * 8;
            uint32_t a[2][4];
#pragma unroll
            for (int mt = 0; mt < 2; mt++) {
                const int r0 = warpM + mt * 16 + g;
                a[mt][0] = f2tf32(As[(r0    ) * SPITCH + k0 + tig    ]);
                a[mt][1] = f2tf32(As[(r0 + 8) * SPITCH + k0 + tig    ]);
                a[mt][2] = f2tf32(As[(r0    ) * SPITCH + k0 + tig + 4]);
                a[mt][3] = f2tf32(As[(r0 + 8) * SPITCH + k0 + tig + 4]);
            }
#pragma unroll
            for (int nt = 0; nt < 8; nt++) {
                const int nr = warpN + nt * 8 + g;
                uint32_t b0 = f2tf32(Ws[nr * SPITCH + k0 + tig    ]);
                uint32_t b1 = f2tf32(Ws[nr * SPITCH + k0 + tig + 4]);
                mma_tf32(acc[0][nt], a[0], b0, b1);
                mma_tf32(acc[1][nt], a[1], b0, b1);
            }
        }
        __syncthreads();
    }

    // ---------------- epilogue ----------------
    const int nbase = bn + warpN;            // 64-aligned => one section/head per warp
    if (MODE == 0) {
        const int sec = nbase >> 9;          // 0:q 1:k 2:v
        const int colbase = nbase & 511;
        const int h = colbase >> 6;
        float* dst = (sec == 0) ? g_q : (sec == 1) ? g_k : g_v;
        // decay factor per row (4 rows per thread)
        float fac[2][2];
#pragma unroll
        for (int mt = 0; mt < 2; mt++)
#pragma unroll
            for (int rh = 0; rh < 2; rh++) {
                const int m = bm + warpM + mt * 16 + g + rh * 8;
                const float c = g_cum[m * HH + h];
                fac[mt][rh] = (sec == 0) ? __expf(c) * 0.125f
                            : (sec == 1) ? __expf(-c) : 1.f;
            }
#pragma unroll
        for (int mt = 0; mt < 2; mt++)
#pragma unroll
            for (int nt = 0; nt < 8; nt++) {
                const int ng = nbase + nt * 8 + tig * 2;
                const float b0 = bias[ng], b1 = bias[ng + 1];
                const int coln = colbase + nt * 8 + tig * 2;
#pragma unroll
                for (int rh = 0; rh < 2; rh++) {
                    const int m = bm + warpM + mt * 16 + g + rh * 8;
                    float v0 = acc[mt][nt][2 * rh    ] + b0;
                    float v1 = acc[mt][nt][2 * rh + 1] + b1;
                    if (sec < 2) {
                        v0 = (v0 > 0.f) ? (v0 + 1.f) : expf(v0);
                        v1 = (v1 > 0.f) ? (v1 + 1.f) : expf(v1);
                        v0 *= fac[mt][rh];
                        v1 *= fac[mt][rh];
                    }
                    float2 o; o.x = v0; o.y = v1;
                    *(float2*)(dst + (size_t)m * DD + coln) = o;
                }
            }
    } else {
#pragma unroll
        for (int mt = 0; mt < 2; mt++)
#pragma unroll
            for (int nt = 0; nt < 8; nt++) {
                const int ng = nbase + nt * 8 + tig * 2;
                const float b0 = bias[ng], b1 = bias[ng + 1];
#pragma unroll
                for (int rh = 0; rh < 2; rh++) {
                    const int m = bm + warpM + mt * 16 + g + rh * 8;
                    float2 o;
                    o.x = acc[mt][nt][2 * rh    ] + b0;
                    o.y = acc[mt][nt][2 * rh + 1] + b1;
                    *(float2*)(g_proj + (size_t)m * DD + ng) = o;
                }
            }
    }
}

// ---------------- decay logits -> log(lambda) ----------------
__global__ __launch_bounds__(256)
void decay_kernel(const float* __restrict__ x, const float* __restrict__ dw,
                  const float* __restrict__ db)
{
    const int m = blockIdx.x;
    const int h = threadIdx.x >> 5;
    const int lane = threadIdx.x & 31;
    const float* xr = x + (size_t)m * DD;
    const float* wr = dw + h * DD;
    float s = 0.f;
    for (int k = lane * 4; k < DD; k += 128) {
        float4 xv = *(const float4*)(xr + k);
        float4 wv = *(const float4*)(wr + k);
        s += xv.x * wv.x + xv.y * wv.y + xv.z * wv.z + xv.w * wv.w;
    }
#pragma unroll
    for (int off = 16; off; off >>= 1) s += __shfl_xor_sync(0xffffffffu, s, off);
    if (lane == 0) {
        float logit = s + db[h];
        float lam = 0.9f + 0.1f / (1.f + expf(-logit));
        g_loglam[m * HH + h] = logf(lam);
    }
}

// ---------------- cumsum of log-lambda along L (per b,h), clipped ----------------
__global__ __launch_bounds__(256)
void cumsum_kernel()
{
    const int b = blockIdx.x >> 3;
    const int h = blockIdx.x & 7;
    const int tid = threadIdx.x;
    float vals[16];
    float s = 0.f;
    const int base = (b * LL + tid * 16) * HH + h;
#pragma unroll
    for (int i = 0; i < 16; i++) { s += g_loglam[base + i * HH]; vals[i] = s; }
    __shared__ float ts[256];
    ts[tid] = s;
    __syncthreads();
    for (int off = 1; off < 256; off <<= 1) {
        float v = (tid >= off) ? ts[tid - off] : 0.f;
        __syncthreads();
        ts[tid] += v;
        __syncthreads();
    }
    const float prev = (tid > 0) ? ts[tid - 1] : 0.f;
#pragma unroll
    for (int i = 0; i < 16; i++) {
        float c = prev + vals[i];
        c = fminf(50.f, fmaxf(-50.f, c));
        g_cum[base + i * HH] = c;
    }
}

// ---------------- per-chunk KV state and k-sum ----------------
__global__ __launch_bounds__(256)
void chunkstate_kernel()
{
    const int c = blockIdx.x & (NC - 1);
    const int h = (blockIdx.x >> 6) & 7;
    const int b = blockIdx.x >> 9;
    __shared__ float ks[8][64];
    __shared__ float vs[8][64];
    const int tid = threadIdx.x;
    const int e0 = (tid >> 4) << 2;
    const int f0 = (tid & 15) << 2;
    float acc[4][4];
#pragma unroll
    for (int i = 0; i < 4; i++)
#pragma unroll
        for (int j = 0; j < 4; j++) acc[i][j] = 0.f;
    float z = 0.f;
    const int rowbase = b * LL + c * CC;

    for (int t0 = 0; t0 < CC; t0 += 8) {
#pragma unroll
        for (int it = 0; it < 2; it++) {
            int idx = tid + it * 256;
            int tt = idx >> 6;
            int ee = idx & 63;
            size_t gg = (size_t)(rowbase + t0 + tt) * DD + h * EE + ee;
            ks[tt][ee] = g_k[gg];
            vs[tt][ee] = g_v[gg];
        }
        __syncthreads();
#pragma unroll
        for (int t = 0; t < 8; t++) {
            float kf[4], vf[4];
#pragma unroll
            for (int i = 0; i < 4; i++) kf[i] = ks[t][e0 + i];
#pragma unroll
            for (int j = 0; j < 4; j++) vf[j] = vs[t][f0 + j];
#pragma unroll
            for (int i = 0; i < 4; i++)
#pragma unroll
                for (int j = 0; j < 4; j++)
                    acc[i][j] = fmaf(kf[i], vf[j], acc[i][j]);
            if (tid < 64) z += ks[t][tid];
        }
        __syncthreads();
    }
    const int bh = b * HH + h;
    const size_t sbase = ((size_t)bh * NC + c) * (EE * EE);
#pragma unroll
    for (int i = 0; i < 4; i++) {
        float4 o; o.x = acc[i][0]; o.y = acc[i][1]; o.z = acc[i][2]; o.w = acc[i][3];
        *(float4*)(g_state + sbase + (e0 + i) * EE + f0) = o;
    }
    if (tid < 64) g_zstate[(bh * NC + c) * EE + tid] = z;
}

// ---------------- exclusive scan over chunks (states + zsums) ----------------
__global__ __launch_bounds__(256)
void statescan_kernel()
{
    const int bh = blockIdx.x >> 4;
    const int split = blockIdx.x & 15;
    const int elem = split * 256 + threadIdx.x;
    size_t base = (size_t)bh * NC * EE * EE + elem;
    float run = 0.f;
#pragma unroll 4
    for (int c = 0; c < NC; c++) {
        float v = g_state[base + (size_t)c * EE * EE];
        g_state[base + (size_t)c * EE * EE] = run;
        run += v;
    }
    if (split == 0 && threadIdx.x < 64) {
        size_t zb = (size_t)bh * NC * EE + threadIdx.x;
        float r = 0.f;
        for (int c = 0; c < NC; c++) {
            float v = g_zstate[zb + (size_t)c * EE];
            g_zstate[zb + (size_t)c * EE] = r;
            r += v;
        }
    }
}

// ---------------- intra-chunk attention + inter via prefix state ----------------
__global__ __launch_bounds__(256)
void intra_kernel()
{
    extern __shared__ float sm[];
    float* qs = sm;
    float* ks = sm + 64 * 68;
    float* vs = sm + 2 * 64 * 68;
    float* As = sm + 3 * 64 * 68;
    float* den_s = sm + 4 * 64 * 68;
    float* zsh = den_s + 64;

    const int c = blockIdx.x & (NC - 1);
    const int h = (blockIdx.x >> 6) & 7;
    const int b = blockIdx.x >> 9;
    const int bh = b * HH + h;
    const int tid = threadIdx.x;
    const int rowbase = b * LL + c * CC;

#pragma unroll
    for (int it = 0; it < 4; it++) {
        int idx = tid + it * 256;
        int t = idx >> 4;
        int e4 = (idx & 15) << 2;
        size_t gg = (size_t)(rowbase + t) * DD + h * EE + e4;
        *(float4*)&qs[t * 68 + e4] = *(const float4*)(g_q + gg);
        *(float4*)&ks[t * 68 + e4] = *(const float4*)(g_k + gg);
        *(float4*)&vs[t * 68 + e4] = *(const float4*)(g_v + gg);
    }
    if (tid < 64) zsh[tid] = g_zstate[(bh * NC + c) * EE + tid];
    __syncthreads();

    const int t0 = (tid >> 4) << 2;
    const int s0 = (tid & 15) << 2;

    {
        float a[4][4];
#pragma unroll
        for (int i = 0; i < 4; i++)
#pragma unroll
            for (int j = 0; j < 4; j++) a[i][j] = 0.f;
        for (int e = 0; e < EE; e += 4) {
            float4 qv[4], kv[4];
#pragma unroll
            for (int i = 0; i < 4; i++) qv[i] = *(const float4*)&qs[(t0 + i) * 68 + e];
#pragma unroll
            for (int j = 0; j < 4; j++) kv[j] = *(const float4*)&ks[(s0 + j) * 68 + e];
#pragma unroll
            for (int i = 0; i < 4; i++)
#pragma unroll
                for (int j = 0; j < 4; j++)
                    a[i][j] += qv[i].x * kv[j].x + qv[i].y * kv[j].y
                             + qv[i].z * kv[j].z + qv[i].w * kv[j].w;
        }
#pragma unroll
        for (int i = 0; i < 4; i++) {
            float r[4];
#pragma unroll
            for (int j = 0; j < 4; j++)
                r[j] = (s0 + j <= t0 + i) ? a[i][j] : 0.f;
            float4 o; o.x = r[0]; o.y = r[1]; o.z = r[2]; o.w = r[3];
            *(float4*)&As[(t0 + i) * 68 + s0] = o;
        }
    }
    __syncthreads();

    {
        const size_t sb = ((size_t)bh * NC + c) * (EE * EE);
#pragma unroll
        for (int it = 0; it < 4; it++) {
            int idx = tid + it * 256;
            int e = idx >> 4;
            int f4 = (idx & 15) << 2;
            *(float4*)&ks[e * 68 + f4] = *(const float4*)(g_state + sb + e * EE + f4);
        }
        if (tid < 64) {
            const int t = tid;
            float s = 0.f;
            for (int s2 = 0; s2 <= t; s2++) s += As[t * 68 + s2];
            for (int e = 0; e < EE; e++) s += qs[t * 68 + e] * zsh[e];
            den_s[t] = 1.f / (s + 1e-6f);
        }
    }
    __syncthreads();

    {
        float acc[4][4];
#pragma unroll
        for (int i = 0; i < 4; i++)
#pragma unroll
            for (int j = 0; j < 4; j++) acc[i][j] = 0.f;

        for (int s = 0; s < CC; s += 4) {
            float av[4][4], vv[4][4];
#pragma unroll
            for (int i = 0; i < 4; i++)
#pragma unroll
                for (int m2 = 0; m2 < 4; m2++)
                    av[i][m2] = As[(t0 + i) * 68 + s + m2];
#pragma unroll
            for (int m2 = 0; m2 < 4; m2++)
#pragma unroll
                for (int j = 0; j < 4; j++)
                    vv[m2][j] = vs[(s + m2) * 68 + s0 + j];
#pragma unroll
            for (int i = 0; i < 4; i++)
#pragma unroll
                for (int m2 = 0; m2 < 4; m2++)
#pragma unroll
                    for (int j = 0; j < 4; j++)
                        acc[i][j] = fmaf(av[i][m2], vv[m2][j], acc[i][j]);
        }
        for (int e = 0; e < EE; e += 4) {
            float qv[4][4], Sv[4][4];
#pragma unroll
            for (int i = 0; i < 4; i++)
#pragma unroll
                for (int m2 = 0; m2 < 4; m2++)
                    qv[i][m2] = qs[(t0 + i) * 68 + e + m2];
#pragma unroll
            for (int m2 = 0; m2 < 4; m2++)
#pragma unroll
                for (int j = 0; j < 4; j++)
                    Sv[m2][j] = ks[(e + m2) * 68 + s0 + j];
#pragma unroll
            for (int i = 0; i < 4; i++)
#pragma unroll
                for (int m2 = 0; m2 < 4; m2++)
#pragma unroll
                    for (int j = 0; j < 4; j++)
                        acc[i][j] = fmaf(qv[i][m2], Sv[m2][j], acc[i][j]);
        }
#pragma unroll
        for (int i = 0; i < 4; i++) {
            const float rd = den_s[t0 + i];
            const int row = rowbase + t0 + i;
            float4 o;
            o.x = acc[i][0] * rd; o.y = acc[i][1] * rd;
            o.z = acc[i][2] * rd; o.w = acc[i][3] * rd;
            *(float4*)(g_attn + (size_t)row * DD + h * EE + s0) = o;
        }
    }
}

// ---------------- RMSNorm ----------------
__global__ __launch_bounds__(128)
void rmsnorm_kernel(const float* __restrict__ scale, float* __restrict__ out)
{
    const int m = blockIdx.x;
    const int tid = threadIdx.x;
    float4 v = *(const float4*)(g_proj + (size_t)m * DD + tid * 4);
    float ss = v.x * v.x + v.y * v.y + v.z * v.z + v.w * v.w;
#pragma unroll
    for (int off = 16; off; off >>= 1) ss += __shfl_xor_sync(0xffffffffu, ss, off);
    __shared__ float ws[4];
    if ((tid & 31) == 0) ws[tid >> 5] = ss;
    __syncthreads();
    float tot = ws[0] + ws[1] + ws[2] + ws[3];
    float rn = rsqrtf(tot * (1.f / DD) + 1e-8f);
    float4 sc = *(const float4*)(scale + tid * 4);
    float4 o;
    o.x = v.x * rn * sc.x; o.y = v.y * rn * sc.y;
    o.z = v.z * rn * sc.z; o.w = v.w * rn * sc.w;
    *(float4*)(out + (size_t)m * DD + tid * 4) = o;
}

// ---------------- launch ----------------
extern "C" void kernel_launch(void* const* d_in, const int* in_sizes, int n_in,
                              void* d_out, int out_size)
{
    const float* x          = (const float*)d_in[0];
    const float* qkv_w      = (const float*)d_in[1];
    const float* qkv_b      = (const float*)d_in[2];
    const float* out_w      = (const float*)d_in[3];
    const float* out_b      = (const float*)d_in[4];
    const float* decay_w    = (const float*)d_in[5];
    const float* decay_b    = (const float*)d_in[6];
    const float* norm_scale = (const float*)d_in[7];
    float* out = (float*)d_out;

    const int gsm = 4 * ASZ * (int)sizeof(float);   // 73728 B (double-buffered A+W)
    cudaFuncSetAttribute(gemm_tc<0>, cudaFuncAttributeMaxDynamicSharedMemorySize, gsm);
    cudaFuncSetAttribute(gemm_tc<1>, cudaFuncAttributeMaxDynamicSharedMemorySize, gsm);

    decay_kernel<<<MM, 256>>>(x, decay_w, decay_b);
    cumsum_kernel<<<BB * HH, 256>>>();

    gemm_tc<0><<<dim3(12, 64), 256, gsm>>>(x, qkv_w, qkv_b);

    chunkstate_kernel<<<BB * HH * NC, 256>>>();
    statescan_kernel<<<BB * HH * 16, 256>>>();

    const int ism = (4 * 64 * 68 + 128) * (int)sizeof(float);   // ~70 KB
    cudaFuncSetAttribute(intra_kernel, cudaFuncAttributeMaxDynamicSharedMemorySize, ism);
    intra_kernel<<<BB * HH * NC, 256, ism>>>();

    gemm_tc<1><<<dim3(4, 64), 256, gsm>>>(nullptr, out_w, out_b);
    rmsnorm_kernel<<<MM, 128>>>(norm_scale, out);
}

// round 4
// speedup vs baseline: 2.6249x; 1.1981x over previous
#include <cuda_runtime.h>
#include <math.h>
#include <stdint.h>

// Problem constants
#define BB 2
#define LL 4096
#define DD 512
#define HH 8
#define EE 64
#define CC 64
#define NC (LL/CC)         // 64
#define MM (BB*LL)         // 8192

// ---------------- scratch (device globals; no allocation) ----------------
__device__ float g_q[MM*DD];
__device__ float g_k[MM*DD];
__device__ float g_v[MM*DD];
__device__ float g_loglam[MM*HH];
__device__ float g_cum[MM*HH];
__device__ float g_state[(size_t)BB*HH*NC*EE*EE];   // S_T[f][e] per chunk -> exclusive prefix
__device__ float g_zstate[BB*HH*NC*EE];
__device__ float g_attn[MM*DD];                     // tf32-rounded attention output
__device__ float g_proj[MM*DD];                     // ALSO reused as rounded-x before gemm1
__device__ float g_wq[3*DD*DD];                     // rounded qkv_w
__device__ float g_wo[DD*DD];                       // rounded out_w
#define g_xr g_proj

// ---------------- helpers ----------------
__device__ __forceinline__ uint32_t f2tf32(float f) {
    uint32_t u;
    asm("cvt.rna.tf32.f32 %0, %1;" : "=r"(u) : "f"(f));
    return u;
}
__device__ __forceinline__ void mma_tf32(float c[4], const uint32_t a[4],
                                         uint32_t b0, uint32_t b1) {
    asm volatile(
        "mma.sync.aligned.m16n8k8.row.col.f32.tf32.tf32.f32 "
        "{%0,%1,%2,%3}, {%4,%5,%6,%7}, {%8,%9}, {%0,%1,%2,%3};"
        : "+f"(c[0]), "+f"(c[1]), "+f"(c[2]), "+f"(c[3])
        : "r"(a[0]), "r"(a[1]), "r"(a[2]), "r"(a[3]), "r"(b0), "r"(b1));
}
__device__ __forceinline__ void cp_async16(uint32_t s, const void* g) {
    asm volatile("cp.async.ca.shared.global [%0], [%1], 16;" :: "r"(s), "l"(g));
}
__device__ __forceinline__ void cp_commit() { asm volatile("cp.async.commit_group;"); }
template<int N>
__device__ __forceinline__ void cp_wait() {
    asm volatile("cp.async.wait_group %0;" :: "n"(N));
}

// ---------------- tensor-core GEMM: C = A @ W^T + bias (pre-rounded operands) ----
#define SPITCH 36
#define ASZ (128 * SPITCH)

template<int MODE>
__global__ __launch_bounds__(256, 2)
void gemm_tc(const float* __restrict__ bias)
{
    extern __shared__ float sm[];
    const float* A = (MODE == 0) ? g_xr : g_attn;
    const float* W = (MODE == 0) ? g_wq : g_wo;

    const int tid  = threadIdx.x;
    const int w    = tid >> 5;
    const int lane = tid & 31;
    const int g    = lane >> 2;
    const int tig  = lane & 3;
    const int warpM = (w & 3) * 32;
    const int warpN = (w >> 2) * 64;
    const int bm = blockIdx.y * 128;
    const int bn = blockIdx.x * 128;

    float acc[2][8][4];
#pragma unroll
    for (int mt = 0; mt < 2; mt++)
#pragma unroll
        for (int nt = 0; nt < 8; nt++)
#pragma unroll
            for (int i = 0; i < 4; i++) acc[mt][nt][i] = 0.f;

    const int lrow0 = tid >> 3;
    const int lcol  = (tid & 7) * 4;

    uint32_t sbase = (uint32_t)__cvta_generic_to_shared((void*)sm);
    auto stage_issue = [&](int kc, int st) {
        uint32_t as = sbase + (uint32_t)(st * 2 * ASZ) * 4u;
        uint32_t ws = as + (uint32_t)ASZ * 4u;
#pragma unroll
        for (int i = 0; i < 4; i++) {
            int row = lrow0 + i * 32;
            cp_async16(as + (uint32_t)(row * SPITCH + lcol) * 4u,
                       A + (size_t)(bm + row) * DD + kc * 32 + lcol);
            cp_async16(ws + (uint32_t)(row * SPITCH + lcol) * 4u,
                       W + (size_t)(bn + row) * DD + kc * 32 + lcol);
        }
        cp_commit();
    };

    stage_issue(0, 0);

    const int NKC = DD / 32;
    for (int kc = 0; kc < NKC; kc++) {
        if (kc + 1 < NKC) { stage_issue(kc + 1, (kc + 1) & 1); cp_wait<1>(); }
        else               { cp_wait<0>(); }
        __syncthreads();

        const float* As = sm + (kc & 1) * 2 * ASZ;
        const float* Ws = As + ASZ;

#pragma unroll
        for (int kk = 0; kk < 4; kk++) {
            const int k0 = kk * 8;
            uint32_t a[2][4];
#pragma unroll
            for (int mt = 0; mt < 2; mt++) {
                const int r0 = warpM + mt * 16 + g;
                a[mt][0] = __float_as_uint(As[(r0    ) * SPITCH + k0 + tig    ]);
                a[mt][1] = __float_as_uint(As[(r0 + 8) * SPITCH + k0 + tig    ]);
                a[mt][2] = __float_as_uint(As[(r0    ) * SPITCH + k0 + tig + 4]);
                a[mt][3] = __float_as_uint(As[(r0 + 8) * SPITCH + k0 + tig + 4]);
            }
#pragma unroll
            for (int nt = 0; nt < 8; nt++) {
                const int nr = warpN + nt * 8 + g;
                uint32_t b0 = __float_as_uint(Ws[nr * SPITCH + k0 + tig    ]);
                uint32_t b1 = __float_as_uint(Ws[nr * SPITCH + k0 + tig + 4]);
                mma_tf32(acc[0][nt], a[0], b0, b1);
                mma_tf32(acc[1][nt], a[1], b0, b1);
            }
        }
        __syncthreads();
    }

    const int nbase = bn + warpN;
    if (MODE == 0) {
        const int sec = nbase >> 9;
        const int colbase = nbase & 511;
        const int h = colbase >> 6;
        float* dst = (sec == 0) ? g_q : (sec == 1) ? g_k : g_v;
        float fac[2][2];
#pragma unroll
        for (int mt = 0; mt < 2; mt++)
#pragma unroll
            for (int rh = 0; rh < 2; rh++) {
                const int m = bm + warpM + mt * 16 + g + rh * 8;
                const float c = g_cum[m * HH + h];
                fac[mt][rh] = (sec == 0) ? __expf(c) * 0.125f
                            : (sec == 1) ? __expf(-c) : 1.f;
            }
#pragma unroll
        for (int mt = 0; mt < 2; mt++)
#pragma unroll
            for (int nt = 0; nt < 8; nt++) {
                const int ng = nbase + nt * 8 + tig * 2;
                const float b0 = bias[ng], b1 = bias[ng + 1];
                const int coln = colbase + nt * 8 + tig * 2;
#pragma unroll
                for (int rh = 0; rh < 2; rh++) {
                    const int m = bm + warpM + mt * 16 + g + rh * 8;
                    float v0 = acc[mt][nt][2 * rh    ] + b0;
                    float v1 = acc[mt][nt][2 * rh + 1] + b1;
                    if (sec < 2) {
                        v0 = (v0 > 0.f) ? (v0 + 1.f) : expf(v0);
                        v1 = (v1 > 0.f) ? (v1 + 1.f) : expf(v1);
                        v0 *= fac[mt][rh];
                        v1 *= fac[mt][rh];
                    }
                    float2 o; o.x = v0; o.y = v1;
                    *(float2*)(dst + (size_t)m * DD + coln) = o;
                }
            }
    } else {
#pragma unroll
        for (int mt = 0; mt < 2; mt++)
#pragma unroll
            for (int nt = 0; nt < 8; nt++) {
                const int ng = nbase + nt * 8 + tig * 2;
                const float b0 = bias[ng], b1 = bias[ng + 1];
#pragma unroll
                for (int rh = 0; rh < 2; rh++) {
                    const int m = bm + warpM + mt * 16 + g + rh * 8;
                    float2 o;
                    o.x = acc[mt][nt][2 * rh    ] + b0;
                    o.y = acc[mt][nt][2 * rh + 1] + b1;
                    *(float2*)(g_proj + (size_t)m * DD + ng) = o;
                }
            }
    }
}

// ---------------- round weights to tf32 ----------------
__global__ __launch_bounds__(256)
void roundw_kernel(const float* __restrict__ qkv_w, const float* __restrict__ out_w)
{
    const int i = blockIdx.x * 256 + threadIdx.x;    // float4 index
    const int NQ = 3 * DD * DD / 4;
    if (i < NQ) {
        float4 v = ((const float4*)qkv_w)[i];
        v.x = __uint_as_float(f2tf32(v.x)); v.y = __uint_as_float(f2tf32(v.y));
        v.z = __uint_as_float(f2tf32(v.z)); v.w = __uint_as_float(f2tf32(v.w));
        ((float4*)g_wq)[i] = v;
    } else {
        const int j = i - NQ;
        float4 v = ((const float4*)out_w)[j];
        v.x = __uint_as_float(f2tf32(v.x)); v.y = __uint_as_float(f2tf32(v.y));
        v.z = __uint_as_float(f2tf32(v.z)); v.w = __uint_as_float(f2tf32(v.w));
        ((float4*)g_wo)[j] = v;
    }
}

// ---------------- decay logits + rounded-x copy ----------------
__global__ __launch_bounds__(256)
void decay_kernel(const float* __restrict__ x, const float* __restrict__ dw,
                  const float* __restrict__ db)
{
    const int m = blockIdx.x;
    const int h = threadIdx.x >> 5;
    const int lane = threadIdx.x & 31;
    const float* xr = x + (size_t)m * DD;
    const float* wr = dw + h * DD;
    float s = 0.f;
    for (int k = lane * 4; k < DD; k += 128) {
        float4 xv = *(const float4*)(xr + k);
        float4 wv = *(const float4*)(wr + k);
        s += xv.x * wv.x + xv.y * wv.y + xv.z * wv.z + xv.w * wv.w;
        if (h == 0) {
            float4 o;
            o.x = __uint_as_float(f2tf32(xv.x));
            o.y = __uint_as_float(f2tf32(xv.y));
            o.z = __uint_as_float(f2tf32(xv.z));
            o.w = __uint_as_float(f2tf32(xv.w));
            *(float4*)(g_xr + (size_t)m * DD + k) = o;
        }
    }
#pragma unroll
    for (int off = 16; off; off >>= 1) s += __shfl_xor_sync(0xffffffffu, s, off);
    if (lane == 0) {
        float logit = s + db[h];
        float lam = 0.9f + 0.1f / (1.f + expf(-logit));
        g_loglam[m * HH + h] = logf(lam);
    }
}

// ---------------- cumsum of log-lambda along L ----------------
__global__ __launch_bounds__(256)
void cumsum_kernel()
{
    const int b = blockIdx.x >> 3;
    const int h = blockIdx.x & 7;
    const int tid = threadIdx.x;
    float vals[16];
    float s = 0.f;
    const int base = (b * LL + tid * 16) * HH + h;
#pragma unroll
    for (int i = 0; i < 16; i++) { s += g_loglam[base + i * HH]; vals[i] = s; }
    __shared__ float ts[256];
    ts[tid] = s;
    __syncthreads();
    for (int off = 1; off < 256; off <<= 1) {
        float v = (tid >= off) ? ts[tid - off] : 0.f;
        __syncthreads();
        ts[tid] += v;
        __syncthreads();
    }
    const float prev = (tid > 0) ? ts[tid - 1] : 0.f;
#pragma unroll
    for (int i = 0; i < 16; i++) {
        float c = prev + vals[i];
        c = fminf(50.f, fmaxf(-50.f, c));
        g_cum[base + i * HH] = c;
    }
}

// ---------------- per-chunk transposed KV state + k-sum (tensor cores) ----------
// Computes S_T[f][e] = sum_t v[t][f] * k[t][e]   (= S[e][f] transposed)
#define TP 65
__global__ __launch_bounds__(128)
void chunkstate_mma()
{
    __shared__ float kT[64 * TP];
    __shared__ float vT[64 * TP];
    const int c = blockIdx.x & (NC - 1);
    const int h = (blockIdx.x >> 6) & 7;
    const int b = blockIdx.x >> 9;
    const int bh = b * HH + h;
    const int tid = threadIdx.x;
    const int w = tid >> 5;
    const int lane = tid & 31;
    const int g = lane >> 2;
    const int tig = lane & 3;
    const int rowbase = b * LL + c * CC;

    // load + transpose
#pragma unroll
    for (int it = 0; it < 8; it++) {
        int idx4 = tid + it * 128;
        int t = idx4 >> 4;
        int e4 = (idx4 & 15) << 2;
        size_t gidx = (size_t)(rowbase + t) * DD + h * EE + e4;
        float4 kv = *(const float4*)(g_k + gidx);
        float4 vv = *(const float4*)(g_v + gidx);
        kT[(e4 + 0) * TP + t] = kv.x; kT[(e4 + 1) * TP + t] = kv.y;
        kT[(e4 + 2) * TP + t] = kv.z; kT[(e4 + 3) * TP + t] = kv.w;
        vT[(e4 + 0) * TP + t] = vv.x; vT[(e4 + 1) * TP + t] = vv.y;
        vT[(e4 + 2) * TP + t] = vv.z; vT[(e4 + 3) * TP + t] = vv.w;
    }
    __syncthreads();

    const int f0 = w * 16;
    float acc[8][4];
#pragma unroll
    for (int nt = 0; nt < 8; nt++)
#pragma unroll
        for (int i = 0; i < 4; i++) acc[nt][i] = 0.f;

#pragma unroll
    for (int kk = 0; kk < 8; kk++) {
        const int k0 = kk * 8;
        uint32_t a[4];
        a[0] = f2tf32(vT[(f0 + g    ) * TP + k0 + tig    ]);
        a[1] = f2tf32(vT[(f0 + g + 8) * TP + k0 + tig    ]);
        a[2] = f2tf32(vT[(f0 + g    ) * TP + k0 + tig + 4]);
        a[3] = f2tf32(vT[(f0 + g + 8) * TP + k0 + tig + 4]);
#pragma unroll
        for (int nt = 0; nt < 8; nt++) {
            uint32_t b0 = f2tf32(kT[(nt * 8 + g) * TP + k0 + tig    ]);
            uint32_t b1 = f2tf32(kT[(nt * 8 + g) * TP + k0 + tig + 4]);
            mma_tf32(acc[nt], a, b0, b1);
        }
    }

    const size_t sb = ((size_t)bh * NC + c) * (EE * EE);
#pragma unroll
    for (int nt = 0; nt < 8; nt++) {
        const int e0 = nt * 8 + tig * 2;
        float2 s0; s0.x = acc[nt][0]; s0.y = acc[nt][1];
        float2 s1; s1.x = acc[nt][2]; s1.y = acc[nt][3];
        *(float2*)(g_state + sb + (f0 + g    ) * EE + e0) = s0;
        *(float2*)(g_state + sb + (f0 + g + 8) * EE + e0) = s1;
    }
    if (tid < 64) {
        float z = 0.f;
#pragma unroll 8
        for (int t = 0; t < CC; t++) z += kT[tid * TP + t];
        g_zstate[(bh * NC + c) * EE + tid] = z;
    }
}

// ---------------- exclusive scan over chunks ----------------
__global__ __launch_bounds__(256)
void statescan_kernel()
{
    const int bh = blockIdx.x >> 4;
    const int split = blockIdx.x & 15;
    const int elem = split * 256 + threadIdx.x;
    size_t base = (size_t)bh * NC * EE * EE + elem;
    float run = 0.f;
#pragma unroll 4
    for (int c = 0; c < NC; c++) {
        float v = g_state[base + (size_t)c * EE * EE];
        g_state[base + (size_t)c * EE * EE] = run;
        run += v;
    }
    if (split == 0 && threadIdx.x < 64) {
        size_t zb = (size_t)bh * NC * EE + threadIdx.x;
        float r = 0.f;
        for (int c = 0; c < NC; c++) {
            float v = g_zstate[zb + (size_t)c * EE];
            g_zstate[zb + (size_t)c * EE] = r;
            r += v;
        }
    }
}

// ---------------- intra-chunk attention (tensor cores) ----------------
// smem: qs[64][68], ks[64][68], Ps[64][68], St[64][68], vT[64][65], z[64], den[64]
#define IP 68
#define OQ 0
#define OK (64*IP)
#define OP (2*64*IP)
#define OS (3*64*IP)
#define OV (4*64*IP)
#define OZ (OV + 64*TP)
#define ODEN (OZ + 64)
#define ISMF (ODEN + 64)

__global__ __launch_bounds__(256)
void intra_mma()
{
    extern __shared__ float sm[];
    const int c = blockIdx.x & (NC - 1);
    const int h = (blockIdx.x >> 6) & 7;
    const int b = blockIdx.x >> 9;
    const int bh = b * HH + h;
    const int tid = threadIdx.x;
    const int w = tid >> 5;
    const int lane = tid & 31;
    const int g = lane >> 2;
    const int tig = lane & 3;
    const int rowbase = b * LL + c * CC;
    const size_t sb = ((size_t)bh * NC + c) * (EE * EE);

    // load q, k (direct), v (transposed), S_T prefix, z prefix
#pragma unroll
    for (int it = 0; it < 4; it++) {
        int idx4 = tid + it * 256;
        int t = idx4 >> 4;
        int e4 = (idx4 & 15) << 2;
        size_t gidx = (size_t)(rowbase + t) * DD + h * EE + e4;
        *(float4*)&sm[OQ + t * IP + e4] = *(const float4*)(g_q + gidx);
        *(float4*)&sm[OK + t * IP + e4] = *(const float4*)(g_k + gidx);
        float4 vv = *(const float4*)(g_v + gidx);
        sm[OV + (e4 + 0) * TP + t] = vv.x; sm[OV + (e4 + 1) * TP + t] = vv.y;
        sm[OV + (e4 + 2) * TP + t] = vv.z; sm[OV + (e4 + 3) * TP + t] = vv.w;
        *(float4*)&sm[OS + t * IP + e4] = *(const float4*)(g_state + sb + idx4 * 4);
    }
    if (tid < 64) sm[OZ + tid] = g_zstate[(bh * NC + c) * EE + tid];
    __syncthreads();

    const int wm = (w & 3) * 16;          // t-stripe
    const int wn = (w >> 2) * 32;         // s/f-stripe

    // phase 1: P[t][s] = sum_e q[t][e] k[s][e], masked s <= t
    {
        float pacc[4][4];
#pragma unroll
        for (int nt = 0; nt < 4; nt++)
#pragma unroll
            for (int i = 0; i < 4; i++) pacc[nt][i] = 0.f;
#pragma unroll
        for (int kk = 0; kk < 8; kk++) {
            const int k0 = kk * 8;
            uint32_t a[4];
            a[0] = f2tf32(sm[OQ + (wm + g    ) * IP + k0 + tig    ]);
            a[1] = f2tf32(sm[OQ + (wm + g + 8) * IP + k0 + tig    ]);
            a[2] = f2tf32(sm[OQ + (wm + g    ) * IP + k0 + tig + 4]);
            a[3] = f2tf32(sm[OQ + (wm + g + 8) * IP + k0 + tig + 4]);
#pragma unroll
            for (int nt = 0; nt < 4; nt++) {
                uint32_t b0 = f2tf32(sm[OK + (wn + nt * 8 + g) * IP + k0 + tig    ]);
                uint32_t b1 = f2tf32(sm[OK + (wn + nt * 8 + g) * IP + k0 + tig + 4]);
                mma_tf32(pacc[nt], a, b0, b1);
            }
        }
#pragma unroll
        for (int nt = 0; nt < 4; nt++) {
            const int scol = wn + nt * 8 + tig * 2;
            const int r0 = wm + g, r1 = wm + g + 8;
            float2 p0, p1;
            p0.x = (scol     <= r0) ? pacc[nt][0] : 0.f;
            p0.y = (scol + 1 <= r0) ? pacc[nt][1] : 0.f;
            p1.x = (scol     <= r1) ? pacc[nt][2] : 0.f;
            p1.y = (scol + 1 <= r1) ? pacc[nt][3] : 0.f;
            *(float2*)&sm[OP + r0 * IP + scol] = p0;
            *(float2*)&sm[OP + r1 * IP + scol] = p1;
        }
    }
    __syncthreads();

    // phase 2: denominators (tf32-rounded P already in smem)
    if (tid < 64) {
        const int t = tid;
        float s = 0.f;
#pragma unroll 8
        for (int s2 = 0; s2 < CC; s2++) s += sm[OP + t * IP + s2];
#pragma unroll 8
        for (int e = 0; e < EE; e++) s += sm[OQ + t * IP + e] * sm[OZ + e];
        sm[ODEN + t] = 1.f / (s + 1e-6f);
    }
    __syncthreads();

    // phase 3: num = P @ v + q @ S; out = num * rden (tf32-rounded for gemm1)
    {
        float acc[4][4];
#pragma unroll
        for (int nt = 0; nt < 4; nt++)
#pragma unroll
            for (int i = 0; i < 4; i++) acc[nt][i] = 0.f;

#pragma unroll
        for (int kk = 0; kk < 8; kk++) {       // P @ v  (K = s)
            const int k0 = kk * 8;
            uint32_t a[4];
            a[0] = f2tf32(sm[OP + (wm + g    ) * IP + k0 + tig    ]);
            a[1] = f2tf32(sm[OP + (wm + g + 8) * IP + k0 + tig    ]);
            a[2] = f2tf32(sm[OP + (wm + g    ) * IP + k0 + tig + 4]);
            a[3] = f2tf32(sm[OP + (wm + g + 8) * IP + k0 + tig + 4]);
#pragma unroll
            for (int nt = 0; nt < 4; nt++) {
                uint32_t b0 = f2tf32(sm[OV + (wn + nt * 8 + g) * TP + k0 + tig    ]);
                uint32_t b1 = f2tf32(sm[OV + (wn + nt * 8 + g) * TP + k0 + tig + 4]);
                mma_tf32(acc[nt], a, b0, b1);
            }
        }
#pragma unroll
        for (int kk = 0; kk < 8; kk++) {       // q @ S_T  (K = e)
            const int k0 = kk * 8;
            uint32_t a[4];
            a[0] = f2tf32(sm[OQ + (wm + g    ) * IP + k0 + tig    ]);
            a[1] = f2tf32(sm[OQ + (wm + g + 8) * IP + k0 + tig    ]);
            a[2] = f2tf32(sm[OQ + (wm + g    ) * IP + k0 + tig + 4]);
            a[3] = f2tf32(sm[OQ + (wm + g + 8) * IP + k0 + tig + 4]);
#pragma unroll
            for (int nt = 0; nt < 4; nt++) {
                uint32_t b0 = f2tf32(sm[OS + (wn + nt * 8 + g) * IP + k0 + tig    ]);
                uint32_t b1 = f2tf32(sm[OS + (wn + nt * 8 + g) * IP + k0 + tig + 4]);
                mma_tf32(acc[nt], a, b0, b1);
            }
        }

        const float rd0 = sm[ODEN + wm + g];
        const float rd1 = sm[ODEN + wm + g + 8];
#pragma unroll
        for (int nt = 0; nt < 4; nt++) {
            const int fcol = wn + nt * 8 + tig * 2;
            float2 o0, o1;
            o0.x = __uint_as_float(f2tf32(acc[nt][0] * rd0));
            o0.y = __uint_as_float(f2tf32(acc[nt][1] * rd0));
            o1.x = __uint_as_float(f2tf32(acc[nt][2] * rd1));
            o1.y = __uint_as_float(f2tf32(acc[nt][3] * rd1));
            *(float2*)(g_attn + (size_t)(rowbase + wm + g    ) * DD + h * EE + fcol) = o0;
            *(float2*)(g_attn + (size_t)(rowbase + wm + g + 8) * DD + h * EE + fcol) = o1;
        }
    }
}

// ---------------- RMSNorm ----------------
__global__ __launch_bounds__(128)
void rmsnorm_kernel(const float* __restrict__ scale, float* __restrict__ out)
{
    const int m = blockIdx.x;
    const int tid = threadIdx.x;
    float4 v = *(const float4*)(g_proj + (size_t)m * DD + tid * 4);
    float ss = v.x * v.x + v.y * v.y + v.z * v.z + v.w * v.w;
#pragma unroll
    for (int off = 16; off; off >>= 1) ss += __shfl_xor_sync(0xffffffffu, ss, off);
    __shared__ float ws[4];
    if ((tid & 31) == 0) ws[tid >> 5] = ss;
    __syncthreads();
    float tot = ws[0] + ws[1] + ws[2] + ws[3];
    float rn = rsqrtf(tot * (1.f / DD) + 1e-8f);
    float4 sc = *(const float4*)(scale + tid * 4);
    float4 o;
    o.x = v.x * rn * sc.x; o.y = v.y * rn * sc.y;
    o.z = v.z * rn * sc.z; o.w = v.w * rn * sc.w;
    *(float4*)(out + (size_t)m * DD + tid * 4) = o;
}

// ---------------- launch ----------------
extern "C" void kernel_launch(void* const* d_in, const int* in_sizes, int n_in,
                              void* d_out, int out_size)
{
    const float* x          = (const float*)d_in[0];
    const float* qkv_w      = (const float*)d_in[1];
    const float* qkv_b      = (const float*)d_in[2];
    const float* out_w      = (const float*)d_in[3];
    const float* out_b      = (const float*)d_in[4];
    const float* decay_w    = (const float*)d_in[5];
    const float* decay_b    = (const float*)d_in[6];
    const float* norm_scale = (const float*)d_in[7];
    float* out = (float*)d_out;

    const int gsm = 4 * ASZ * (int)sizeof(float);
    cudaFuncSetAttribute(gemm_tc<0>, cudaFuncAttributeMaxDynamicSharedMemorySize, gsm);
    cudaFuncSetAttribute(gemm_tc<1>, cudaFuncAttributeMaxDynamicSharedMemorySize, gsm);
    const int ism = ISMF * (int)sizeof(float);
    cudaFuncSetAttribute(intra_mma, cudaFuncAttributeMaxDynamicSharedMemorySize, ism);

    decay_kernel<<<MM, 256>>>(x, decay_w, decay_b);            // #1 (also rounds x -> g_xr)
    cumsum_kernel<<<BB * HH, 256>>>();                         // #2
    roundw_kernel<<<1024, 256>>>(qkv_w, out_w);                // #3
    gemm_tc<0><<<dim3(12, 64), 256, gsm>>>(qkv_b);             // #4  <- ncu capture slot
    chunkstate_mma<<<BB * HH * NC, 128>>>();                   // #5
    statescan_kernel<<<BB * HH * 16, 256>>>();                 // #6
    intra_mma<<<BB * HH * NC, 256, ism>>>();                   // #7
    gemm_tc<1><<<dim3(4, 64), 256, gsm>>>(out_b);              // #8
    rmsnorm_kernel<<<MM, 128>>>(norm_scale, out);              // #9
}